// round 2
// baseline (speedup 1.0000x reference)
#include <cuda_runtime.h>
#include <cuda_bf16.h>

// LoRALayerNorm: out = layernorm(x) * scale + shift
//   scale[i] = sum_r A_s[i,r] * B_s[r,i] * (ALPHA/RANK)
//   shift[i] = sum_r A_h[i,r] * B_h[r,i] * (ALPHA/RANK)
// Shapes: x [B=2, S=4096, N=8192] fp32; A [N,4]; B [4,N].
// Strategy: kernel 1 builds scale/shift vectors (tiny). Kernel 2 is a
// one-read-one-write register-resident LayerNorm: 512 thr/row, 16 floats
// (4x float4) per thread, block reduction, fused affine on writeback.

#define RANK 4
#define SCALING 2.0f   /* ALPHA(8) / RANK(4) */
#define EPS 1e-5f
#define MAX_N 8192

__device__ float g_scale[MAX_N];
__device__ float g_shift[MAX_N];

__global__ void lora_vec_kernel(const float* __restrict__ As,
                                const float* __restrict__ Bs,
                                const float* __restrict__ Ah,
                                const float* __restrict__ Bh,
                                int N) {
    int i = blockIdx.x * blockDim.x + threadIdx.x;
    if (i >= N) return;
    float s = 0.f, h = 0.f;
#pragma unroll
    for (int r = 0; r < RANK; r++) {
        s += As[i * RANK + r] * Bs[r * N + i];
        h += Ah[i * RANK + r] * Bh[r * N + i];
    }
    g_scale[i] = s * SCALING;
    g_shift[i] = h * SCALING;
}

// One block per row. 512 threads, each owns 4 float4 = 16 floats of the row.
__global__ __launch_bounds__(512, 2)
void ln_kernel(const float* __restrict__ x, float* __restrict__ out, int N) {
    const int tid = threadIdx.x;
    const int NV4 = N >> 2;             // 2048 float4 per row
    const size_t row_off = (size_t)blockIdx.x * (size_t)N;
    const float4* __restrict__ xr = (const float4*)(x + row_off);
    float4* __restrict__ orow = (float4*)(out + row_off);

    // Load 4 float4 into registers; accumulate sum and sum of squares.
    float4 v[4];
    float sum = 0.f, sq = 0.f;
#pragma unroll
    for (int it = 0; it < 4; it++) {
        int idx = tid + it * 512;       // idx < NV4 (N == 8192)
        float4 t = xr[idx];
        v[it] = t;
        sum += t.x + t.y + t.z + t.w;
        sq  += t.x * t.x + t.y * t.y + t.z * t.z + t.w * t.w;
    }

    // Block reduction: warp shuffle + smem across 16 warps.
    __shared__ float red_s[16];
    __shared__ float red_q[16];
#pragma unroll
    for (int o = 16; o > 0; o >>= 1) {
        sum += __shfl_xor_sync(0xffffffffu, sum, o);
        sq  += __shfl_xor_sync(0xffffffffu, sq, o);
    }
    const int warp = tid >> 5, lane = tid & 31;
    if (lane == 0) { red_s[warp] = sum; red_q[warp] = sq; }
    __syncthreads();
    if (warp == 0) {
        float s = (lane < 16) ? red_s[lane] : 0.f;
        float q = (lane < 16) ? red_q[lane] : 0.f;
#pragma unroll
        for (int o = 8; o > 0; o >>= 1) {
            s += __shfl_xor_sync(0xffffffffu, s, o);
            q += __shfl_xor_sync(0xffffffffu, q, o);
        }
        if (lane == 0) { red_s[0] = s; red_q[0] = q; }
    }
    __syncthreads();

    const float inv_n = 1.0f / (float)N;
    const float mean = red_s[0] * inv_n;
    const float var = fmaxf(red_q[0] * inv_n - mean * mean, 0.f);
    const float rstd = rsqrtf(var + EPS);

    const float4* __restrict__ sc4 = (const float4*)g_scale;
    const float4* __restrict__ sh4 = (const float4*)g_shift;
#pragma unroll
    for (int it = 0; it < 4; it++) {
        int idx = tid + it * 512;
        float4 t = v[it];
        float4 sc = sc4[idx];
        float4 sh = sh4[idx];
        float4 o;
        o.x = (t.x - mean) * rstd * sc.x + sh.x;
        o.y = (t.y - mean) * rstd * sc.y + sh.y;
        o.z = (t.z - mean) * rstd * sc.z + sh.z;
        o.w = (t.w - mean) * rstd * sc.w + sh.w;
        orow[idx] = o;
    }
}

extern "C" void kernel_launch(void* const* d_in, const int* in_sizes, int n_in,
                              void* d_out, int out_size) {
    const float* x  = (const float*)d_in[0];
    const float* As = (const float*)d_in[1];
    const float* Bs = (const float*)d_in[2];
    const float* Ah = (const float*)d_in[3];
    const float* Bh = (const float*)d_in[4];
    float* out = (float*)d_out;

    // B is [RANK, N] -> N = elems / RANK
    const int N = in_sizes[2] / RANK;           // 8192
    const int rows = (int)((size_t)in_sizes[0] / (size_t)N);  // 8192

    lora_vec_kernel<<<(N + 255) / 256, 256>>>(As, Bs, Ah, Bh, N);
    ln_kernel<<<rows, 512>>>(x, out, N);
}

// round 4
// speedup vs baseline: 1.0030x; 1.0030x over previous
#include <cuda_runtime.h>
#include <cuda_bf16.h>

// LoRALayerNorm: out = layernorm(x) * scale + shift
//   scale[i] = sum_r A_s[i,r] * B_s[r,i] * (ALPHA/RANK)
// Shapes: x [2,4096,8192] fp32; A [N,4]; B [4,N].
// R3: 256 thr/block, 8x float4/thread, 4 CTAs/SM for barrier-gap coverage;
// streaming hints (__ldcs/__stcs) on the x/out streams; vectorized lora kernel.

#define RANK 4
#define SCALING 2.0f   /* ALPHA(8) / RANK(4) */
#define EPS 1e-5f
#define MAX_N 8192

__device__ float g_scale[MAX_N];
__device__ float g_shift[MAX_N];

__global__ void lora_vec_kernel(const float* __restrict__ As,
                                const float* __restrict__ Bs,
                                const float* __restrict__ Ah,
                                const float* __restrict__ Bh,
                                int N) {
    int i = blockIdx.x * blockDim.x + threadIdx.x;
    if (i >= N) return;
    float4 a = *(const float4*)(As + i * RANK);
    float s = a.x * Bs[i] + a.y * Bs[N + i] + a.z * Bs[2 * N + i] + a.w * Bs[3 * N + i];
    float4 h = *(const float4*)(Ah + i * RANK);
    float t = h.x * Bh[i] + h.y * Bh[N + i] + h.z * Bh[2 * N + i] + h.w * Bh[3 * N + i];
    g_scale[i] = s * SCALING;
    g_shift[i] = t * SCALING;
}

// One block per row. 256 threads, each owns 8 float4 = 32 floats of the row.
#define LN_T 256
#define LN_ITER 8

__global__ __launch_bounds__(LN_T, 4)
void ln_kernel(const float* __restrict__ x, float* __restrict__ out, int N) {
    const int tid = threadIdx.x;
    const size_t row_off = (size_t)blockIdx.x * (size_t)N;
    const float4* __restrict__ xr = (const float4*)(x + row_off);
    float4* __restrict__ orow = (float4*)(out + row_off);

    // Front-batched streaming loads; accumulate sum and sum of squares.
    float4 v[LN_ITER];
    float sum = 0.f, sq = 0.f;
#pragma unroll
    for (int it = 0; it < LN_ITER; it++) {
        v[it] = __ldcs(&xr[tid + it * LN_T]);
    }
#pragma unroll
    for (int it = 0; it < LN_ITER; it++) {
        float4 t = v[it];
        sum += t.x + t.y + t.z + t.w;
        sq  += t.x * t.x + t.y * t.y + t.z * t.z + t.w * t.w;
    }

    // Block reduction: warp shuffle + smem across 8 warps.
    __shared__ float red_s[8];
    __shared__ float red_q[8];
#pragma unroll
    for (int o = 16; o > 0; o >>= 1) {
        sum += __shfl_xor_sync(0xffffffffu, sum, o);
        sq  += __shfl_xor_sync(0xffffffffu, sq, o);
    }
    const int warp = tid >> 5, lane = tid & 31;
    if (lane == 0) { red_s[warp] = sum; red_q[warp] = sq; }
    __syncthreads();
    if (warp == 0) {
        float s = (lane < 8) ? red_s[lane] : 0.f;
        float q = (lane < 8) ? red_q[lane] : 0.f;
#pragma unroll
        for (int o = 4; o > 0; o >>= 1) {
            s += __shfl_xor_sync(0xffffffffu, s, o);
            q += __shfl_xor_sync(0xffffffffu, q, o);
        }
        if (lane == 0) { red_s[0] = s; red_q[0] = q; }
    }
    __syncthreads();

    const float inv_n = 1.0f / (float)N;
    const float mean = red_s[0] * inv_n;
    const float var = fmaxf(red_q[0] * inv_n - mean * mean, 0.f);
    const float rstd = rsqrtf(var + EPS);

    const float4* __restrict__ sc4 = (const float4*)g_scale;
    const float4* __restrict__ sh4 = (const float4*)g_shift;
#pragma unroll
    for (int it = 0; it < LN_ITER; it++) {
        const int idx = tid + it * LN_T;
        float4 t = v[it];
        float4 sc = __ldg(&sc4[idx]);
        float4 sh = __ldg(&sh4[idx]);
        float4 o;
        o.x = (t.x - mean) * rstd * sc.x + sh.x;
        o.y = (t.y - mean) * rstd * sc.y + sh.y;
        o.z = (t.z - mean) * rstd * sc.z + sh.z;
        o.w = (t.w - mean) * rstd * sc.w + sh.w;
        __stcs(&orow[idx], o);
    }
}

extern "C" void kernel_launch(void* const* d_in, const int* in_sizes, int n_in,
                              void* d_out, int out_size) {
    const float* x  = (const float*)d_in[0];
    const float* As = (const float*)d_in[1];
    const float* Bs = (const float*)d_in[2];
    const float* Ah = (const float*)d_in[3];
    const float* Bh = (const float*)d_in[4];
    float* out = (float*)d_out;

    const int N = in_sizes[2] / RANK;                          // 8192
    const int rows = (int)((size_t)in_sizes[0] / (size_t)N);   // 8192

    lora_vec_kernel<<<(N + 255) / 256, 256>>>(As, Bs, Ah, Bh, N);
    ln_kernel<<<rows, LN_T>>>(x, out, N);
}